// round 15
// baseline (speedup 1.0000x reference)
#include <cuda_runtime.h>
#include <cuda_fp16.h>
#include <cstdint>

#define B_  8
#define T_  2048
#define D_  256
#define BQ  128
#define BK  64
#define NIT 32          // T_/BK
#define NTH 256

// ---- PRE-SWIZZLED f16 tile images (exact smem layout, bulk-copyable)
// Q tiles:  [b][qt 0..15]  65536 B each (128 rows x 512 B, chunk s at ((s^(r&7))<<4))
// K tiles:  [b][et 0..31]  32768 B each (64 rows x 512 B)
// Q is pre-scaled by log2(e); Q keeps an f16 lo-image (2-chain split), K is hi-only.
__device__ __align__(256) unsigned char g_qhi[(size_t)B_*16*65536];
__device__ __align__(256) unsigned char g_qlo[(size_t)B_*16*65536];
__device__ __align__(256) unsigned char g_khi[(size_t)B_*32*32768];

__device__ __forceinline__ uint32_t h2pack(__half a, __half b){
    return (uint32_t)__half_as_ushort(a) | ((uint32_t)__half_as_ushort(b) << 16);
}
__device__ __forceinline__ float ex2f(float x){
    float r; asm("ex2.approx.f32 %0, %1;" : "=f"(r) : "f"(x)); return r;
}
__device__ __forceinline__ uint32_t h2ex2(uint32_t x){    // ex2 on packed half2
    uint32_t r; asm("ex2.approx.f16x2 %0, %1;" : "=r"(r) : "r"(x)); return r;
}

// one pass over dec (also writes out[...,0:256]) and enc; writes swizzled tiles
__global__ void pk_all(const float* __restrict__ dec, const float* __restrict__ enc,
                       float* __restrict__ out){
    size_t g = (size_t)blockIdx.x * NTH + threadIdx.x;
    const size_t QU = (size_t)B_*T_*D_/4;
    bool isq = (g < QU);
    size_t q = isq ? g : g - QU;
    float4 v = isq ? ((const float4*)dec)[q] : ((const float4*)enc)[q];
    if (isq){
        size_t row = q >> 6, c4 = q & 63;
        ((float4*)out)[row*128 + c4] = v;      // dec copy -> out[...,0:256]
        const float L2E = 1.4426950408889634f; // Q in log2 domain
        v.x *= L2E; v.y *= L2E; v.z *= L2E; v.w *= L2E;
    }
    __half hx=__float2half_rn(v.x), hy=__float2half_rn(v.y);
    __half hz=__float2half_rn(v.z), hw=__float2half_rn(v.w);
    uint2 hi = make_uint2(h2pack(hx,hy), h2pack(hz,hw));

    int c4  = (int)(q & 63);
    int row = (int)(q >> 6);          // global row 0..16383
    int b   = row >> 11, rr = row & 2047;
    uint32_t s = (uint32_t)(c4 >> 1), half8 = (uint32_t)(c4 & 1) * 8u;
    if (isq){
        __half lx=__float2half_rn(v.x-__half2float(hx)), ly=__float2half_rn(v.y-__half2float(hy));
        __half lz=__float2half_rn(v.z-__half2float(hz)), lw=__float2half_rn(v.w-__half2float(hw));
        uint2 lo = make_uint2(h2pack(lx,ly), h2pack(lz,lw));
        uint32_t tile = (uint32_t)(rr >> 7), r = (uint32_t)(rr & 127);
        uint32_t off = ((uint32_t)(b*16) + tile)*65536u + r*512u + ((s ^ (r & 7)) << 4) + half8;
        *(uint2*)(g_qhi + off) = hi;
        *(uint2*)(g_qlo + off) = lo;
    } else {
        uint32_t tile = (uint32_t)(rr >> 6), r = (uint32_t)(rr & 63);
        uint32_t off = ((uint32_t)(b*32) + tile)*32768u + r*512u + ((s ^ (r & 7)) << 4) + half8;
        *(uint2*)(g_khi + off) = hi;
    }
}

// ---------------- base-ISA tensor / bulk-async primitives ------------------
__device__ __forceinline__ void ldsm4(uint32_t r[4], uint32_t a){
    asm volatile("ldmatrix.sync.aligned.m8n8.x4.shared.b16 {%0,%1,%2,%3}, [%4];"
        : "=r"(r[0]),"=r"(r[1]),"=r"(r[2]),"=r"(r[3]) : "r"(a));
}
__device__ __forceinline__ void ldsm4t(uint32_t r[4], uint32_t a){
    asm volatile("ldmatrix.sync.aligned.m8n8.x4.trans.shared.b16 {%0,%1,%2,%3}, [%4];"
        : "=r"(r[0]),"=r"(r[1]),"=r"(r[2]),"=r"(r[3]) : "r"(a));
}
__device__ __forceinline__ void mma16816(float d[4], const uint32_t a[4], const uint32_t b[2]){
    asm volatile("mma.sync.aligned.m16n8k16.row.col.f32.f16.f16.f32 "
        "{%0,%1,%2,%3}, {%4,%5,%6,%7}, {%8,%9}, {%0,%1,%2,%3};"
        : "+f"(d[0]),"+f"(d[1]),"+f"(d[2]),"+f"(d[3])
        : "r"(a[0]),"r"(a[1]),"r"(a[2]),"r"(a[3]), "r"(b[0]),"r"(b[1]));
}
__device__ __forceinline__ void bulkcp(uint32_t dst, const void* src, uint32_t bytes, uint32_t mbar){
    uint64_t ga; asm("cvta.to.global.u64 %0, %1;" : "=l"(ga) : "l"(src));
    asm volatile("cp.async.bulk.shared::cta.global.mbarrier::complete_tx::bytes [%0], [%1], %2, [%3];"
        :: "r"(dst), "l"(ga), "r"(bytes), "r"(mbar) : "memory");
}
#define MBI(a,c)   asm volatile("mbarrier.init.shared.b64 [%0], %1;" :: "r"(a), "r"(c) : "memory")
#define MBEX(a,n)  asm volatile("mbarrier.arrive.expect_tx.shared.b64 _, [%0], %1;" :: "r"(a), "r"(n) : "memory")
#define MBARR(a)   asm volatile("mbarrier.arrive.shared.b64 _, [%0];" :: "r"(a) : "memory")
#define MBW(a,ph)  asm volatile("{\n\t.reg .pred P1;\n\tWL_%=:\n\t" \
    "mbarrier.try_wait.parity.acquire.cta.shared::cta.b64 P1, [%0], %1, 0x989680;\n\t" \
    "@P1 bra.uni WD_%=;\n\tbra.uni WL_%=;\n\tWD_%=:\n\t}" :: "r"(a), "r"(ph) : "memory")

// ---- smem layout: 3-stage K pipeline ---------------------------------------
#define SM_QHI  0                    // 128 rows = 65536
#define SM_QLO  65536
#define SM_K0   131072               // 3 stages x 32768
#define SM_BAR  229376               // 7 mbarriers
#define SM_TOT  229440
#define MB_FQ   (SM_BAR + 0)
#define MB_FK(s) (SM_BAR + 8  + 8*(s))   // full  barriers, stages 0..2
#define MB_EK(s) (SM_BAR + 32 + 8*(s))   // empty barriers, stages 0..2

__global__ __launch_bounds__(NTH) void attn_main(float* __restrict__ out)
{
    extern __shared__ char smem[];
    const uint32_t smb = (uint32_t)__cvta_generic_to_shared(smem);
    const int tid = threadIdx.x, w = tid >> 5, lane = tid & 31;
    const int qt = blockIdx.x, b = blockIdx.y, t0 = qt * BQ;
    const int g = lane >> 3, lr = lane & 7;

    if (tid == 0){
        MBI(smb + MB_FQ, 1);
        #pragma unroll
        for (int s = 0; s < 3; s++){ MBI(smb + MB_FK(s), 1); MBI(smb + MB_EK(s), 8); }
    }
    __syncthreads();

    if (tid == 0){
        MBEX(smb + MB_FQ, 131072u);
        bulkcp(smb + SM_QHI, g_qhi + (size_t)(b*16 + qt)*65536u, 65536u, smb + MB_FQ);
        bulkcp(smb + SM_QLO, g_qlo + (size_t)(b*16 + qt)*65536u, 65536u, smb + MB_FQ);
        #pragma unroll
        for (int n = 0; n < 2; n++){                        // tiles 0,1 up-front
            MBEX(smb + MB_FK(n), 32768u);
            bulkcp(smb + SM_K0 + n*32768u,
                   g_khi + (size_t)(b*32 + n)*32768u, 32768u, smb + MB_FK(n));
        }
    }

    const uint32_t qhiR = smb + SM_QHI + (uint32_t)(16*w + (g&1)*8 + lr)*512u;
    const uint32_t qloR = qhiR + (SM_QLO - SM_QHI);
    const uint32_t kr1  = (uint32_t)((g>>1)*8 + lr)*512u;   // GEMM1 B rows
    const uint32_t kr2  = (uint32_t)((g&1)*8 + lr)*512u;    // GEMM2 B rows

    // constant "ones column" B fragment -> MMA computes rowsum(P) into accl
    uint32_t onesB[2];
    onesB[0] = onesB[1] = (lane < 4) ? 0x3C003C00u : 0u;

    float mA = -1e30f, mB = -1e30f;
    float accl[4] = {0.f, 0.f, 0.f, 0.f};
    float acc[32][4];
    #pragma unroll
    for (int j = 0; j < 32; j++){ acc[j][0]=0.f; acc[j][1]=0.f; acc[j][2]=0.f; acc[j][3]=0.f; }

    float S[8][4];

    MBW(smb + MB_FQ, 0);            // Q resident
    MBW(smb + MB_FK(0), 0);         // K tile 0 resident

    // ---- prologue: GEMM1(0) -> S -------------------------------------------
    {
        #pragma unroll
        for (int j = 0; j < 8; j++){ S[j][0]=0.f; S[j][1]=0.f; S[j][2]=0.f; S[j][3]=0.f; }
        const uint32_t kb0 = smb + SM_K0;
        #pragma unroll
        for (int c = 0; c < 16; c++){
            uint32_t qoff = (uint32_t)((((g>>1) + 2*c) ^ lr) << 4);
            uint32_t ah[4], al[4];
            ldsm4(ah, qhiR + qoff);
            ldsm4(al, qloR + qoff);
            uint32_t koff = (uint32_t)((((g&1) + 2*c) ^ lr) << 4);
            uint32_t bh[4][4];
            #pragma unroll
            for (int p = 0; p < 4; p++) ldsm4(bh[p], kb0 + kr1 + (uint32_t)p*8192u + koff);
            #pragma unroll
            for (int p = 0; p < 4; p++){ mma16816(S[2*p], ah, bh[p]); mma16816(S[2*p+1], ah, bh[p]+2); }
            #pragma unroll
            for (int p = 0; p < 4; p++){ mma16816(S[2*p], al, bh[p]); mma16816(S[2*p+1], al, bh[p]+2); }
        }
    }

    #pragma unroll 1
    for (int it = 0; it < NIT; it++){
        // producer: issue K(it+2)
        if (tid == 0 && it + 2 < NIT){
            int n = it + 2, st = n % 3;
            if (n >= 3) MBW(smb + MB_EK(st), (n/3 - 1) & 1);
            MBEX(smb + MB_FK(st), 32768u);
            bulkcp(smb + SM_K0 + (uint32_t)st*32768u,
                   g_khi + (size_t)(b*32 + n)*32768u, 32768u, smb + MB_FK(st));
        }

        // ---- online softmax on S(it), log2 domain --------------------------
        float bmA = -1e30f, bmB = -1e30f;
        #pragma unroll
        for (int j = 0; j < 8; j++){
            bmA = fmaxf(bmA, fmaxf(S[j][0], S[j][1]));
            bmB = fmaxf(bmB, fmaxf(S[j][2], S[j][3]));
        }
        bmA = fmaxf(bmA, __shfl_xor_sync(0xffffffffu, bmA, 1));
        bmA = fmaxf(bmA, __shfl_xor_sync(0xffffffffu, bmA, 2));
        bmB = fmaxf(bmB, __shfl_xor_sync(0xffffffffu, bmB, 1));
        bmB = fmaxf(bmB, __shfl_xor_sync(0xffffffffu, bmB, 2));

        float mnA = fmaxf(mA, bmA), mnB = fmaxf(mB, bmB);
        float alphaA = ex2f(mA - mnA), alphaB = ex2f(mB - mnB);
        mA = mnA; mB = mnB;

        uint32_t ph[8][2];
        #pragma unroll
        for (int j = 0; j < 8; j++){
            __half2 dA = __floats2half2_rn(S[j][0] - mnA, S[j][1] - mnA);
            __half2 dB = __floats2half2_rn(S[j][2] - mnB, S[j][3] - mnB);
            ph[j][0] = h2ex2(*(uint32_t*)&dA);
            ph[j][1] = h2ex2(*(uint32_t*)&dB);
        }

        if (!__all_sync(0xffffffffu, (alphaA == 1.f) & (alphaB == 1.f))){
            #pragma unroll
            for (int j = 0; j < 32; j++){
                acc[j][0] *= alphaA; acc[j][1] *= alphaA;
                acc[j][2] *= alphaB; acc[j][3] *= alphaB;
            }
            accl[0] *= alphaA; accl[1] *= alphaA;
            accl[2] *= alphaB; accl[3] *= alphaB;
        }

        const bool haveNext = (it + 1 < NIT);
        const uint32_t kb  = smb + SM_K0 + (uint32_t)(it % 3)*32768u;        // GEMM2 src
        const uint32_t kbn = smb + SM_K0 + (uint32_t)((it + 1) % 3)*32768u;  // GEMM1 src

        if (haveNext) MBW(smb + MB_FK((it + 1) % 3), ((it + 1) / 3) & 1);

        // S registers are dead (consumed into ph) -> reuse for S(it+1)
        #pragma unroll
        for (int j = 0; j < 8; j++){ S[j][0]=0.f; S[j][1]=0.f; S[j][2]=0.f; S[j][3]=0.f; }

        // ---- fused block: GEMM1(it+1) interleaved 4:1 with GEMM2(it) -------
        #pragma unroll
        for (int c = 0; c < 16; c++){
            if (haveNext){
                uint32_t qoff = (uint32_t)((((g>>1) + 2*c) ^ lr) << 4);
                uint32_t ah[4], al[4];
                ldsm4(ah, qhiR + qoff);
                ldsm4(al, qloR + qoff);
                uint32_t koff = (uint32_t)((((g&1) + 2*c) ^ lr) << 4);
                uint32_t bh[4][4];
                #pragma unroll
                for (int p = 0; p < 4; p++) ldsm4(bh[p], kbn + kr1 + (uint32_t)p*8192u + koff);
                #pragma unroll
                for (int p = 0; p < 4; p++){ mma16816(S[2*p], ah, bh[p]); mma16816(S[2*p+1], ah, bh[p]+2); }
                #pragma unroll
                for (int p = 0; p < 4; p++){ mma16816(S[2*p], al, bh[p]); mma16816(S[2*p+1], al, bh[p]+2); }
            }
            if ((c & 3) == 3){
                int kc = c >> 2;
                uint32_t a[4] = { ph[2*kc][0], ph[2*kc][1], ph[2*kc+1][0], ph[2*kc+1][1] };
                mma16816(accl, a, onesB);
                uint32_t rof = kr2 + (uint32_t)kc*8192u;
                #pragma unroll
                for (int jj = 0; jj < 32; jj += 2){
                    uint32_t bb[4];
                    ldsm4t(bb, kb + rof + (uint32_t)((((g>>1) + jj) ^ lr) << 4));
                    mma16816(acc[jj],   a, bb);
                    mma16816(acc[jj+1], a, bb+2);
                }
            }
        }
        if (lane == 0) MBARR(smb + MB_EK(it % 3));   // done with K(it)
    }

    // ---- epilogue: broadcast l from col-0 lanes, write context -------------
    {
        float lA = __shfl_sync(0xffffffffu, accl[0], lane & ~3);
        float lB = __shfl_sync(0xffffffffu, accl[2], lane & ~3);
        int rA = 16*w + (lane >> 2);
        float ivA = 1.f / lA, ivB = 1.f / lB;
        float* oA = out + ((size_t)(b*T_ + t0 + rA))    *(size_t)(2*D_) + D_ + (lane&3)*2;
        float* oB = out + ((size_t)(b*T_ + t0 + rA + 8))*(size_t)(2*D_) + D_ + (lane&3)*2;
        #pragma unroll
        for (int j = 0; j < 32; j++){
            *(float2*)(oA + 8*j) = make_float2(acc[j][0]*ivA, acc[j][1]*ivA);
            *(float2*)(oB + 8*j) = make_float2(acc[j][2]*ivB, acc[j][3]*ivB);
        }
    }
}

extern "C" void kernel_launch(void* const* d_in, const int* in_sizes, int n_in,
                              void* d_out, int out_size)
{
    const float* enc = (const float*)d_in[0];  // encoder_outputs [8,2048,256]
    const float* dec = (const float*)d_in[1];  // decoder_outputs [8,2048,256]
    float* out = (float*)d_out;                // [8,2048,512]
    (void)in_sizes; (void)n_in; (void)out_size;

    const int quads2 = 2 * B_*T_*D_/4;         // dec + enc quads
    pk_all<<<quads2/NTH, NTH>>>(dec, enc, out);

    cudaFuncSetAttribute(attn_main, cudaFuncAttributeMaxDynamicSharedMemorySize, SM_TOT);
    dim3 grid(T_/BQ, B_);                      // (16, 8) = 128 CTAs, single wave
    attn_main<<<grid, NTH, SM_TOT>>>(out);
}

// round 16
// speedup vs baseline: 1.1107x; 1.1107x over previous
#include <cuda_runtime.h>
#include <cuda_fp16.h>
#include <cstdint>

#define B_  8
#define T_  2048
#define D_  256
#define BQ  128
#define BK  64
#define NIT 32          // T_/BK
#define NTH 256

// ---- PRE-SWIZZLED f16 tile images (exact smem layout, bulk-copyable)
// Q tiles:  [b][qt 0..15]  65536 B each (128 rows x 512 B, chunk s at ((s^(r&7))<<4))
// K tiles:  [b][et 0..31]  32768 B each (64 rows x 512 B)
// Q is pre-scaled by log2(e); Q keeps an f16 lo-image (2-chain split), K is hi-only.
__device__ __align__(256) unsigned char g_qhi[(size_t)B_*16*65536];
__device__ __align__(256) unsigned char g_qlo[(size_t)B_*16*65536];
__device__ __align__(256) unsigned char g_khi[(size_t)B_*32*32768];

__device__ __forceinline__ uint32_t h2pack(__half a, __half b){
    return (uint32_t)__half_as_ushort(a) | ((uint32_t)__half_as_ushort(b) << 16);
}
__device__ __forceinline__ float ex2f(float x){
    float r; asm("ex2.approx.f32 %0, %1;" : "=f"(r) : "f"(x)); return r;
}
__device__ __forceinline__ uint32_t h2ex2(uint32_t x){    // ex2 on packed half2
    uint32_t r; asm("ex2.approx.f16x2 %0, %1;" : "=r"(r) : "r"(x)); return r;
}

// one pass over dec (also writes out[...,0:256]) and enc; writes swizzled tiles
__global__ void pk_all(const float* __restrict__ dec, const float* __restrict__ enc,
                       float* __restrict__ out){
    size_t g = (size_t)blockIdx.x * NTH + threadIdx.x;
    const size_t QU = (size_t)B_*T_*D_/4;
    bool isq = (g < QU);
    size_t q = isq ? g : g - QU;
    float4 v = isq ? ((const float4*)dec)[q] : ((const float4*)enc)[q];
    if (isq){
        size_t row = q >> 6, c4 = q & 63;
        ((float4*)out)[row*128 + c4] = v;      // dec copy -> out[...,0:256]
        const float L2E = 1.4426950408889634f; // Q in log2 domain
        v.x *= L2E; v.y *= L2E; v.z *= L2E; v.w *= L2E;
    }
    __half hx=__float2half_rn(v.x), hy=__float2half_rn(v.y);
    __half hz=__float2half_rn(v.z), hw=__float2half_rn(v.w);
    uint2 hi = make_uint2(h2pack(hx,hy), h2pack(hz,hw));

    int c4  = (int)(q & 63);
    int row = (int)(q >> 6);          // global row 0..16383
    int b   = row >> 11, rr = row & 2047;
    uint32_t s = (uint32_t)(c4 >> 1), half8 = (uint32_t)(c4 & 1) * 8u;
    if (isq){
        __half lx=__float2half_rn(v.x-__half2float(hx)), ly=__float2half_rn(v.y-__half2float(hy));
        __half lz=__float2half_rn(v.z-__half2float(hz)), lw=__float2half_rn(v.w-__half2float(hw));
        uint2 lo = make_uint2(h2pack(lx,ly), h2pack(lz,lw));
        uint32_t tile = (uint32_t)(rr >> 7), r = (uint32_t)(rr & 127);
        uint32_t off = ((uint32_t)(b*16) + tile)*65536u + r*512u + ((s ^ (r & 7)) << 4) + half8;
        *(uint2*)(g_qhi + off) = hi;
        *(uint2*)(g_qlo + off) = lo;
    } else {
        uint32_t tile = (uint32_t)(rr >> 6), r = (uint32_t)(rr & 63);
        uint32_t off = ((uint32_t)(b*32) + tile)*32768u + r*512u + ((s ^ (r & 7)) << 4) + half8;
        *(uint2*)(g_khi + off) = hi;
    }
}

// ---------------- base-ISA tensor / bulk-async primitives ------------------
__device__ __forceinline__ void ldsm4(uint32_t r[4], uint32_t a){
    asm volatile("ldmatrix.sync.aligned.m8n8.x4.shared.b16 {%0,%1,%2,%3}, [%4];"
        : "=r"(r[0]),"=r"(r[1]),"=r"(r[2]),"=r"(r[3]) : "r"(a));
}
__device__ __forceinline__ void ldsm4t(uint32_t r[4], uint32_t a){
    asm volatile("ldmatrix.sync.aligned.m8n8.x4.trans.shared.b16 {%0,%1,%2,%3}, [%4];"
        : "=r"(r[0]),"=r"(r[1]),"=r"(r[2]),"=r"(r[3]) : "r"(a));
}
__device__ __forceinline__ void mma16816(float d[4], const uint32_t a[4], const uint32_t b[2]){
    asm volatile("mma.sync.aligned.m16n8k16.row.col.f32.f16.f16.f32 "
        "{%0,%1,%2,%3}, {%4,%5,%6,%7}, {%8,%9}, {%0,%1,%2,%3};"
        : "+f"(d[0]),"+f"(d[1]),"+f"(d[2]),"+f"(d[3])
        : "r"(a[0]),"r"(a[1]),"r"(a[2]),"r"(a[3]), "r"(b[0]),"r"(b[1]));
}
__device__ __forceinline__ void bulkcp(uint32_t dst, const void* src, uint32_t bytes, uint32_t mbar){
    uint64_t ga; asm("cvta.to.global.u64 %0, %1;" : "=l"(ga) : "l"(src));
    asm volatile("cp.async.bulk.shared::cta.global.mbarrier::complete_tx::bytes [%0], [%1], %2, [%3];"
        :: "r"(dst), "l"(ga), "r"(bytes), "r"(mbar) : "memory");
}
#define MBI(a,c)   asm volatile("mbarrier.init.shared.b64 [%0], %1;" :: "r"(a), "r"(c) : "memory")
#define MBEX(a,n)  asm volatile("mbarrier.arrive.expect_tx.shared.b64 _, [%0], %1;" :: "r"(a), "r"(n) : "memory")
#define MBARR(a)   asm volatile("mbarrier.arrive.shared.b64 _, [%0];" :: "r"(a) : "memory")
#define MBW(a,ph)  asm volatile("{\n\t.reg .pred P1;\n\tWL_%=:\n\t" \
    "mbarrier.try_wait.parity.acquire.cta.shared::cta.b64 P1, [%0], %1, 0x989680;\n\t" \
    "@P1 bra.uni WD_%=;\n\tbra.uni WL_%=;\n\tWD_%=:\n\t}" :: "r"(a), "r"(ph) : "memory")

// ---- smem layout: 3-stage K pipeline ---------------------------------------
#define SM_QHI  0                    // 128 rows = 65536
#define SM_QLO  65536
#define SM_K0   131072               // 3 stages x 32768
#define SM_BAR  229376               // 7 mbarriers
#define SM_TOT  229440
#define MB_FQ   (SM_BAR + 0)
#define MB_FK(s) (SM_BAR + 8  + 8*(s))   // full  barriers, stages 0..2
#define MB_EK(s) (SM_BAR + 32 + 8*(s))   // empty barriers, stages 0..2

__global__ __launch_bounds__(NTH) void attn_main(float* __restrict__ out)
{
    extern __shared__ char smem[];
    const uint32_t smb = (uint32_t)__cvta_generic_to_shared(smem);
    const int tid = threadIdx.x, w = tid >> 5, lane = tid & 31;
    const int qt = blockIdx.x, b = blockIdx.y, t0 = qt * BQ;
    const int g = lane >> 3, lr = lane & 7;

    if (tid == 0){
        MBI(smb + MB_FQ, 1);
        #pragma unroll
        for (int s = 0; s < 3; s++){ MBI(smb + MB_FK(s), 1); MBI(smb + MB_EK(s), 8); }
    }
    __syncthreads();

    if (tid == 0){
        MBEX(smb + MB_FQ, 131072u);
        bulkcp(smb + SM_QHI, g_qhi + (size_t)(b*16 + qt)*65536u, 65536u, smb + MB_FQ);
        bulkcp(smb + SM_QLO, g_qlo + (size_t)(b*16 + qt)*65536u, 65536u, smb + MB_FQ);
        #pragma unroll
        for (int n = 0; n < 2; n++){                        // tiles 0,1 up-front
            MBEX(smb + MB_FK(n), 32768u);
            bulkcp(smb + SM_K0 + n*32768u,
                   g_khi + (size_t)(b*32 + n)*32768u, 32768u, smb + MB_FK(n));
        }
    }

    const uint32_t qhiR = smb + SM_QHI + (uint32_t)(16*w + (g&1)*8 + lr)*512u;
    const uint32_t qloR = qhiR + (SM_QLO - SM_QHI);
    const uint32_t kr1  = (uint32_t)((g>>1)*8 + lr)*512u;   // GEMM1 B rows
    const uint32_t kr2  = (uint32_t)((g&1)*8 + lr)*512u;    // GEMM2 B rows

    // constant "ones column" B fragment -> MMA computes rowsum(P) into accl
    uint32_t onesB[2];
    onesB[0] = onesB[1] = (lane < 4) ? 0x3C003C00u : 0u;

    float mA = -1e30f, mB = -1e30f;
    float accl[4] = {0.f, 0.f, 0.f, 0.f};   // [0]: rowsum rA, [2]: rB
    float acc[32][4];
    #pragma unroll
    for (int j = 0; j < 32; j++){ acc[j][0]=0.f; acc[j][1]=0.f; acc[j][2]=0.f; acc[j][3]=0.f; }

    MBW(smb + MB_FQ, 0);    // Q resident

    #pragma unroll 1
    for (int it = 0; it < NIT; it++){
        if (tid == 0 && it + 2 < NIT){
            int n = it + 2, st = n % 3;
            if (n >= 3) MBW(smb + MB_EK(st), (n/3 - 1) & 1);
            MBEX(smb + MB_FK(st), 32768u);
            bulkcp(smb + SM_K0 + (uint32_t)st*32768u,
                   g_khi + (size_t)(b*32 + n)*32768u, 32768u, smb + MB_FK(st));
        }
        const int st = it % 3;
        MBW(smb + MB_FK(st), (it/3) & 1);

        const uint32_t kb = smb + SM_K0 + (uint32_t)st*32768u;

        // ---- GEMM1: S[16q x 64e] = Qhi*Khi + Qlo*Khi (log2 domain) --------
        float S[8][4];
        #pragma unroll
        for (int j = 0; j < 8; j++){ S[j][0]=0.f; S[j][1]=0.f; S[j][2]=0.f; S[j][3]=0.f; }

        #pragma unroll
        for (int c = 0; c < 16; c++){
            uint32_t qoff = (uint32_t)((((g>>1) + 2*c) ^ lr) << 4);
            uint32_t ah[4], al[4];
            ldsm4(ah, qhiR + qoff);
            ldsm4(al, qloR + qoff);
            uint32_t koff = (uint32_t)((((g&1) + 2*c) ^ lr) << 4);
            uint32_t bh[4][4];
            #pragma unroll
            for (int p = 0; p < 4; p++){
                uint32_t rof = kr1 + (uint32_t)p*8192u;
                ldsm4(bh[p], kb + rof + koff);
            }
            #pragma unroll
            for (int p = 0; p < 4; p++){ mma16816(S[2*p], ah, bh[p]); mma16816(S[2*p+1], ah, bh[p]+2); }
            #pragma unroll
            for (int p = 0; p < 4; p++){ mma16816(S[2*p], al, bh[p]); mma16816(S[2*p+1], al, bh[p]+2); }
        }

        // ---- online softmax max-reduce (rows rA=16w+(lane>>2), rB=rA+8) ---
        float bmA = -1e30f, bmB = -1e30f;
        #pragma unroll
        for (int j = 0; j < 8; j++){
            bmA = fmaxf(bmA, fmaxf(S[j][0], S[j][1]));
            bmB = fmaxf(bmB, fmaxf(S[j][2], S[j][3]));
        }
        bmA = fmaxf(bmA, __shfl_xor_sync(0xffffffffu, bmA, 1));
        bmA = fmaxf(bmA, __shfl_xor_sync(0xffffffffu, bmA, 2));
        bmB = fmaxf(bmB, __shfl_xor_sync(0xffffffffu, bmB, 1));
        bmB = fmaxf(bmB, __shfl_xor_sync(0xffffffffu, bmB, 2));

        float mnA = fmaxf(mA, bmA), mnB = fmaxf(mB, bmB);
        float alphaA = ex2f(mA - mnA), alphaB = ex2f(mB - mnB);
        mA = mnA; mB = mnB;

        if (!__all_sync(0xffffffffu, (alphaA == 1.f) & (alphaB == 1.f))){
            #pragma unroll
            for (int j = 0; j < 32; j++){
                acc[j][0] *= alphaA; acc[j][1] *= alphaA;
                acc[j][2] *= alphaB; acc[j][3] *= alphaB;
            }
            accl[0] *= alphaA; accl[1] *= alphaA;
            accl[2] *= alphaB; accl[3] *= alphaB;
        }

        // ---- GEMM2 with ex2/convert pipelined one kc-group ahead ------------
        // pair kc needs ph[2kc..2kc+1]; compute pair kc+1's MUFUs before
        // issuing kc's MMA burst so their latency retires under MMA issue.
        uint32_t ph[8][2];
        {   // pair 0 up-front
            __half2 dA0 = __floats2half2_rn(S[0][0] - mnA, S[0][1] - mnA);
            __half2 dB0 = __floats2half2_rn(S[0][2] - mnB, S[0][3] - mnB);
            __half2 dA1 = __floats2half2_rn(S[1][0] - mnA, S[1][1] - mnA);
            __half2 dB1 = __floats2half2_rn(S[1][2] - mnB, S[1][3] - mnB);
            ph[0][0] = h2ex2(*(uint32_t*)&dA0);  ph[0][1] = h2ex2(*(uint32_t*)&dB0);
            ph[1][0] = h2ex2(*(uint32_t*)&dA1);  ph[1][1] = h2ex2(*(uint32_t*)&dB1);
        }
        #pragma unroll
        for (int kc = 0; kc < 4; kc++){
            if (kc < 3){   // pre-compute pair kc+1 (independent of kc's MMAs)
                int j0 = 2*kc + 2, j1 = 2*kc + 3;
                __half2 dA0 = __floats2half2_rn(S[j0][0] - mnA, S[j0][1] - mnA);
                __half2 dB0 = __floats2half2_rn(S[j0][2] - mnB, S[j0][3] - mnB);
                __half2 dA1 = __floats2half2_rn(S[j1][0] - mnA, S[j1][1] - mnA);
                __half2 dB1 = __floats2half2_rn(S[j1][2] - mnB, S[j1][3] - mnB);
                ph[j0][0] = h2ex2(*(uint32_t*)&dA0);  ph[j0][1] = h2ex2(*(uint32_t*)&dB0);
                ph[j1][0] = h2ex2(*(uint32_t*)&dA1);  ph[j1][1] = h2ex2(*(uint32_t*)&dB1);
            }
            uint32_t a[4] = { ph[2*kc][0], ph[2*kc][1], ph[2*kc+1][0], ph[2*kc+1][1] };
            mma16816(accl, a, onesB);
            uint32_t rof = kr2 + (uint32_t)kc*8192u;
            #pragma unroll
            for (int jj = 0; jj < 32; jj += 2){
                uint32_t bb[4];
                ldsm4t(bb, kb + rof + (uint32_t)((((g>>1) + jj) ^ lr) << 4));
                mma16816(acc[jj],   a, bb);
                mma16816(acc[jj+1], a, bb+2);
            }
        }
        if (lane == 0) MBARR(smb + MB_EK(st));   // done with Khi(it)
    }

    // ---- epilogue: broadcast l from col-0 lanes, write context -------------
    {
        float lA = __shfl_sync(0xffffffffu, accl[0], lane & ~3);
        float lB = __shfl_sync(0xffffffffu, accl[2], lane & ~3);
        int rA = 16*w + (lane >> 2);
        float ivA = 1.f / lA, ivB = 1.f / lB;
        float* oA = out + ((size_t)(b*T_ + t0 + rA))    *(size_t)(2*D_) + D_ + (lane&3)*2;
        float* oB = out + ((size_t)(b*T_ + t0 + rA + 8))*(size_t)(2*D_) + D_ + (lane&3)*2;
        #pragma unroll
        for (int j = 0; j < 32; j++){
            *(float2*)(oA + 8*j) = make_float2(acc[j][0]*ivA, acc[j][1]*ivA);
            *(float2*)(oB + 8*j) = make_float2(acc[j][2]*ivB, acc[j][3]*ivB);
        }
    }
}

extern "C" void kernel_launch(void* const* d_in, const int* in_sizes, int n_in,
                              void* d_out, int out_size)
{
    const float* enc = (const float*)d_in[0];  // encoder_outputs [8,2048,256]
    const float* dec = (const float*)d_in[1];  // decoder_outputs [8,2048,256]
    float* out = (float*)d_out;                // [8,2048,512]
    (void)in_sizes; (void)n_in; (void)out_size;

    const int quads2 = 2 * B_*T_*D_/4;         // dec + enc quads
    pk_all<<<quads2/NTH, NTH>>>(dec, enc, out);

    cudaFuncSetAttribute(attn_main, cudaFuncAttributeMaxDynamicSharedMemorySize, SM_TOT);
    dim3 grid(T_/BQ, B_);                      // (16, 8) = 128 CTAs, single wave
    attn_main<<<grid, NTH, SM_TOT>>>(out);
}